// round 7
// baseline (speedup 1.0000x reference)
#include <cuda_runtime.h>

#define BN_EPS 1e-5f

// ---------------- device-global scratch (no allocations allowed) ----------------
__device__ __align__(16) float d_W1f[216];            // conv1 folded weights [oc][27]
__device__ __align__(16) float d_b1f[8];              // conv1 folded bias
__device__ __align__(16) float d_W2f[3456];           // conv2 folded weights [t][ic][oc16]
__device__ __align__(16) float d_b2f[16];             // conv2 folded bias
__device__ __align__(16) float d_h1[8 * 48 * 48 * 48 * 8];  // stage-1 output, channels-last

typedef unsigned long long u64;

// packed fp32x2 FMA (Blackwell sm_100+): 2 FMAs per instruction
__device__ __forceinline__ u64 ffma2(u64 a, u64 b, u64 c) {
    u64 d;
    asm("fma.rn.f32x2 %0, %1, %2, %3;" : "=l"(d) : "l"(a), "l"(b), "l"(c));
    return d;
}

union F2U { float2 f; u64 u; };
union F4U { float4 f4; u64 u[2]; float f[4]; };

// ---------------- prep: fold BN into conv weights/biases ----------------
__global__ void prep_kernel(const float* __restrict__ W1, const float* __restrict__ b1,
                            const float* __restrict__ g1, const float* __restrict__ be1,
                            const float* __restrict__ m1, const float* __restrict__ v1,
                            const float* __restrict__ W2, const float* __restrict__ b2,
                            const float* __restrict__ g2, const float* __restrict__ be2,
                            const float* __restrict__ m2, const float* __restrict__ v2) {
    int tid = threadIdx.x;
    // conv1: W1 layout DHWIO [3,3,3,1,8] -> linear t*8+oc. Store transposed [oc][t].
    for (int i = tid; i < 216; i += blockDim.x) {
        int oc = i / 27, t = i % 27;
        float s = g1[oc] * rsqrtf(v1[oc] + BN_EPS);
        d_W1f[i] = W1[t * 8 + oc] * s;
    }
    if (tid < 8) {
        float s = g1[tid] * rsqrtf(v1[tid] + BN_EPS);
        d_b1f[tid] = (b1[tid] - m1[tid]) * s + be1[tid];
    }
    // conv2: W2 layout [3,3,3,8,16] -> linear (t*8+ic)*16+oc (kept as-is, scaled by oc)
    for (int i = tid; i < 3456; i += blockDim.x) {
        int oc = i % 16;
        float s = g2[oc] * rsqrtf(v2[oc] + BN_EPS);
        d_W2f[i] = W2[i] * s;
    }
    if (tid < 16) {
        float s = g2[tid] * rsqrtf(v2[tid] + BN_EPS);
        d_b2f[tid] = (b2[tid] - m2[tid]) * s + be2[tid];
    }
}

// ---------------- kernel 1: conv1(1->8) + BN + ReLU + maxpool2 ----------------
// grid: (216 tiles, 8 batch), block 512. Pooled tile 8x8x8 -> conv 16^3 -> input 18^3.
// Packed f32x2 over x-position pairs: per thread 4x4x4 input cube held as 32 float2
// (aligned pairs are free), weights duplicated (w,w) in smem -> uniform LDS.64.
__global__ __launch_bounds__(512) void k1_kernel(const float* __restrict__ x) {
    __shared__ float s_in[18 * 18 * 18];
    __shared__ float2 s_wp[216];  // (w,w) duplicated, [oc][27]
    __shared__ float s_b[8];

    const int tid = threadIdx.x;
    const int b = blockIdx.y;
    const int tl = blockIdx.x;
    const int tbx = tl % 6, tby = (tl / 6) % 6, tbz = tl / 36;

    if (tid < 216) {
        float w = d_W1f[tid];
        s_wp[tid] = make_float2(w, w);
    }
    if (tid < 8) s_b[tid] = d_b1f[tid];

    const int oz = tbz * 16 - 1, oy = tby * 16 - 1, ox = tbx * 16 - 1;
    const float* xb = x + (long)b * 96 * 96 * 96;
    for (int i = tid; i < 18 * 18 * 18; i += 512) {
        int lz = i / 324, r = i - lz * 324, ly = r / 18, lx = r - ly * 18;
        int gz = oz + lz, gy = oy + ly, gx = ox + lx;
        float v = 0.f;
        if ((unsigned)gz < 96u && (unsigned)gy < 96u && (unsigned)gx < 96u)
            v = xb[(gz * 96 + gy) * 96 + gx];
        s_in[i] = v;
    }
    __syncthreads();

    const int px = tid & 7, py = (tid >> 3) & 7, pz = tid >> 6;

    // preload this thread's 4x4x4 input cube as 16 rows x 2 aligned float2
    // row r = z*4+y holds cols {0,1} and {2,3}; element (z,y,c) = input(2pz+z, 2py+y, 2px+c)
    float2 in2[32];
#pragma unroll
    for (int lz = 0; lz < 4; ++lz)
#pragma unroll
        for (int ly = 0; ly < 4; ++ly) {
            const int base = ((2 * pz + lz) * 18 + 2 * py + ly) * 18 + 2 * px;  // even
            const float2* sp = reinterpret_cast<const float2*>(s_in + base);
            in2[(lz * 4 + ly) * 2 + 0] = sp[0];
            in2[(lz * 4 + ly) * 2 + 1] = sp[1];
        }

    const long out_base =
        ((((long)b * 48 + tbz * 8 + pz) * 48 + tby * 8 + py) * 48 + tbx * 8 + px) * 8;

#pragma unroll 1
    for (int pass = 0; pass < 2; ++pass) {
        // acc[o][j]: o = oc within pass, j = position pair (dz,dy); lanes = (dx0,dx1)
        u64 acc[4][4];
#pragma unroll
        for (int o = 0; o < 4; ++o)
#pragma unroll
            for (int j = 0; j < 4; ++j) acc[o][j] = 0ull;

#pragma unroll 1
        for (int tz = 0; tz < 3; ++tz) {
#pragma unroll 1
            for (int ty = 0; ty < 3; ++ty) {
                // 4 input rows for this (tz,ty): r(dz,dy) = (tz+dz)*4 + (ty+dy)
                u64 p0[4], p1[4], p2[4];
#pragma unroll
                for (int dz = 0; dz < 2; ++dz)
#pragma unroll
                    for (int dy = 0; dy < 2; ++dy) {
                        const int j = dz * 2 + dy;
                        const int r = (tz + dz) * 4 + (ty + dy);
                        F2U a, bb, c;
                        a.f = in2[r * 2];        // cols (0,1)
                        bb.f = in2[r * 2 + 1];   // cols (2,3)
                        c.f = make_float2(a.f.y, bb.f.x);  // cols (1,2)
                        p0[j] = a.u;
                        p1[j] = c.u;
                        p2[j] = bb.u;
                    }
#pragma unroll
                for (int o = 0; o < 4; ++o) {
                    const int oc = pass * 4 + o;
                    const float2* wp = s_wp + oc * 27 + (tz * 3 + ty) * 3;
                    F2U w0, w1, w2;
                    w0.f = wp[0]; w1.f = wp[1]; w2.f = wp[2];
#pragma unroll
                    for (int j = 0; j < 4; ++j) {
                        acc[o][j] = ffma2(p0[j], w0.u, acc[o][j]);
                        acc[o][j] = ffma2(p1[j], w1.u, acc[o][j]);
                        acc[o][j] = ffma2(p2[j], w2.u, acc[o][j]);
                    }
                }
            }
        }

        float res[4];
#pragma unroll
        for (int o = 0; o < 4; ++o) {
            F2U u0, u1, u2, u3;
            u0.u = acc[o][0]; u1.u = acc[o][1]; u2.u = acc[o][2]; u3.u = acc[o][3];
            float m = fmaxf(fmaxf(fmaxf(u0.f.x, u0.f.y), fmaxf(u1.f.x, u1.f.y)),
                            fmaxf(fmaxf(u2.f.x, u2.f.y), fmaxf(u3.f.x, u3.f.y)));
            res[o] = fmaxf(m + s_b[pass * 4 + o], 0.f);  // relu(max+bias)==pool(relu(bn))
        }
        float4 v4 = make_float4(res[0], res[1], res[2], res[3]);
        *reinterpret_cast<float4*>(d_h1 + out_base + pass * 4) = v4;
    }
}

// ---------------- kernel 2: conv2(8->16) + BN + ReLU + maxpool2 + FC(16->5) ------
// grid: (216 tiles, 8 batch), block 512 = 8^3 conv positions. Pooled tile 4^3.
__global__ __launch_bounds__(512) void k2_kernel(const float* __restrict__ Wf,
                                                 const float* __restrict__ bf,
                                                 float* __restrict__ out) {
    __shared__ float4 s_buf[2048];  // 32 KB: input tile (2000 f4), later conv results (8192 f)
    __shared__ float s_w2[3456];
    __shared__ float2 s_b2[8];
    __shared__ float s_wf[80];
    __shared__ float s_bf[5];

    const int tid = threadIdx.x;
    const int b = blockIdx.y;
    const int tl = blockIdx.x;
    const int tbx = tl % 6, tby = (tl / 6) % 6, tbz = tl / 36;

    for (int i = tid; i < 3456; i += 512) s_w2[i] = d_W2f[i];
    if (tid < 8) s_b2[tid] = reinterpret_cast<const float2*>(d_b2f)[tid];
    if (tid < 80) s_wf[tid] = Wf[tid];
    if (tid < 5) s_bf[tid] = bf[tid];

    const int oz = tbz * 8 - 1, oy = tby * 8 - 1, ox = tbx * 8 - 1;
    const float4* h14 =
        reinterpret_cast<const float4*>(d_h1) + (long)b * 48 * 48 * 48 * 2;
    for (int i = tid; i < 2000; i += 512) {
        int v = i >> 1, h = i & 1;
        int lz = v / 100, r = v - lz * 100, ly = r / 10, lx = r - ly * 10;
        int gz = oz + lz, gy = oy + ly, gx = ox + lx;
        float4 val = make_float4(0.f, 0.f, 0.f, 0.f);
        if ((unsigned)gz < 48u && (unsigned)gy < 48u && (unsigned)gx < 48u)
            val = h14[((gz * 48 + gy) * 48 + gx) * 2 + h];
        s_buf[i] = val;
    }
    __syncthreads();

    const int cx = tid & 7, cy = (tid >> 3) & 7, cz = tid >> 6;

    // 16 output channels as 8 packed f32x2 accumulators, bias-initialized
    u64 acc[8];
#pragma unroll
    for (int j = 0; j < 8; ++j) {
        F2U u; u.f = s_b2[j]; acc[j] = u.u;
    }

    const float4* s_in4 = s_buf;
#pragma unroll 1
    for (int tz = 0; tz < 3; ++tz) {
#pragma unroll 1
        for (int ty = 0; ty < 3; ++ty) {
            const float4* iprow = s_in4 + (((cz + tz) * 10 + cy + ty) * 10 + cx) * 2;
            const float* wrow = s_w2 + ((tz * 3 + ty) * 3) * 128;
#pragma unroll
            for (int tx = 0; tx < 3; ++tx) {
                F4U i0, i1;
                i0.f4 = iprow[tx * 2];
                i1.f4 = iprow[tx * 2 + 1];
                const float* wt = wrow + tx * 128;  // [ic][oc16]
#pragma unroll
                for (int ic = 0; ic < 8; ++ic) {
                    const float iv = (ic < 4) ? i0.f[ic] : i1.f[ic - 4];
                    F2U sp; sp.f = make_float2(iv, iv);
                    const float* wp = wt + ic * 16;
#pragma unroll
                    for (int q = 0; q < 4; ++q) {
                        F4U wv;
                        wv.f4 = *reinterpret_cast<const float4*>(wp + q * 4);
                        acc[q * 2]     = ffma2(sp.u, wv.u[0], acc[q * 2]);
                        acc[q * 2 + 1] = ffma2(sp.u, wv.u[1], acc[q * 2 + 1]);
                    }
                }
            }
        }
    }
    __syncthreads();  // all input-tile reads complete before overwriting s_buf

    // stash relu'd conv results for cross-thread pooling
    float* s_conv = reinterpret_cast<float*>(s_buf);
    {
        const int base = tid * 16;
#pragma unroll
        for (int j = 0; j < 8; ++j) {
            F2U u; u.u = acc[j];
            s_conv[base + 2 * j]     = fmaxf(u.f.x, 0.f);
            s_conv[base + 2 * j + 1] = fmaxf(u.f.y, 0.f);
        }
    }
    __syncthreads();

    if (tid < 64) {
        const int px = tid & 3, py = (tid >> 2) & 3, pz = tid >> 4;
        float m[16];
#pragma unroll
        for (int k = 0; k < 16; ++k) m[k] = 0.f;  // post-relu values are >= 0
#pragma unroll
        for (int dz = 0; dz < 2; ++dz)
#pragma unroll
            for (int dy = 0; dy < 2; ++dy)
#pragma unroll
                for (int dx = 0; dx < 2; ++dx) {
                    const float* p =
                        s_conv + (((2 * pz + dz) * 8 + 2 * py + dy) * 8 + 2 * px + dx) * 16;
#pragma unroll
                    for (int k = 0; k < 16; ++k) m[k] = fmaxf(m[k], p[k]);
                }
        float o[5];
#pragma unroll
        for (int n = 0; n < 5; ++n) o[n] = s_bf[n];
#pragma unroll
        for (int k = 0; k < 16; ++k)
#pragma unroll
            for (int n = 0; n < 5; ++n) o[n] = fmaf(m[k], s_wf[k * 5 + n], o[n]);

        const long ob =
            ((((long)b * 24 + tbz * 4 + pz) * 24 + tby * 4 + py) * 24 + tbx * 4 + px) * 5;
#pragma unroll
        for (int n = 0; n < 5; ++n) out[ob + n] = o[n];
    }
}

// ---------------- launch ----------------
extern "C" void kernel_launch(void* const* d_in, const int* in_sizes, int n_in,
                              void* d_out, int out_size) {
    const float* x   = (const float*)d_in[0];
    const float* W1  = (const float*)d_in[1];
    const float* b1  = (const float*)d_in[2];
    const float* g1  = (const float*)d_in[3];
    const float* be1 = (const float*)d_in[4];
    const float* m1  = (const float*)d_in[5];
    const float* v1  = (const float*)d_in[6];
    const float* W2  = (const float*)d_in[7];
    const float* b2  = (const float*)d_in[8];
    const float* g2  = (const float*)d_in[9];
    const float* be2 = (const float*)d_in[10];
    const float* m2  = (const float*)d_in[11];
    const float* v2  = (const float*)d_in[12];
    const float* Wf  = (const float*)d_in[13];
    const float* bf  = (const float*)d_in[14];
    float* out = (float*)d_out;

    prep_kernel<<<1, 512>>>(W1, b1, g1, be1, m1, v1, W2, b2, g2, be2, m2, v2);
    k1_kernel<<<dim3(216, 8), 512>>>(x);
    k2_kernel<<<dim3(216, 8), 512>>>(Wf, bf, out);
}